// round 1
// baseline (speedup 1.0000x reference)
#include <cuda_runtime.h>
#include <math.h>
#include <stdint.h>

// ---------------- problem constants ----------------
#define D_MODEL 256
#define D_FFN   1024
#define N_HEADS 8
#define N_LEVELS 4
#define N_POINTS 4
#define HEAD_DIM 32
#define LQ      21760
#define BATCH   2
#define M_ROWS  (BATCH * LQ)   // 43520

// level tables (fixed by setup_inputs)
__device__ __constant__ int c_H[4]  = {128, 64, 32, 16};
__device__ __constant__ int c_W[4]  = {128, 64, 32, 16};
__device__ __constant__ int c_ST[4] = {0, 16384, 20480, 21504};

// ---------------- scratch (device globals; no allocations allowed) ----------------
__device__ float g_value[(size_t)M_ROWS * D_MODEL];
__device__ float g_offs [(size_t)M_ROWS * D_MODEL];
__device__ float g_attn [(size_t)M_ROWS * 128];
__device__ float g_samp [(size_t)M_ROWS * D_MODEL];
__device__ float g_t1   [(size_t)M_ROWS * D_MODEL];
__device__ float g_h    [(size_t)M_ROWS * D_MODEL];
__device__ float g_ffn  [(size_t)M_ROWS * D_FFN];
__device__ float g_t2   [(size_t)M_ROWS * D_MODEL];

// ---------------- generic fp32 GEMM: C = (A (+A2)) @ W + bias (+res), optional relu ----
// A: [M,K] row-major, W: [K,N] row-major. Tiles: BM=BN=64, BK=16, 256 threads, 4x4/thread.
template <bool A2F, bool RESF, bool RELUF>
__global__ void __launch_bounds__(256) gemm_kernel(
    const float* __restrict__ A, const float* __restrict__ A2,
    const float* __restrict__ W, const float* __restrict__ bias,
    const float* __restrict__ res, float* __restrict__ C,
    int M, int N, int K)
{
    __shared__ float As[16][64];
    __shared__ float Ws[16][64];

    const int tid = threadIdx.x;
    const int bm = blockIdx.y * 64;
    const int bn = blockIdx.x * 64;
    const int tx = tid & 15;       // col group
    const int ty = tid >> 4;       // row group

    // load mapping
    const int la_m = tid >> 2;           // 0..63
    const int la_k = (tid & 3) * 4;      // 0,4,8,12
    const int lw_k = tid >> 4;           // 0..15
    const int lw_n = (tid & 15) * 4;     // 0..60

    float acc[4][4];
#pragma unroll
    for (int i = 0; i < 4; i++)
#pragma unroll
        for (int j = 0; j < 4; j++) acc[i][j] = 0.f;

    for (int k0 = 0; k0 < K; k0 += 16) {
        float4 a = *(const float4*)(A + (size_t)(bm + la_m) * K + k0 + la_k);
        if (A2F) {
            float4 a2 = *(const float4*)(A2 + (size_t)(bm + la_m) * K + k0 + la_k);
            a.x += a2.x; a.y += a2.y; a.z += a2.z; a.w += a2.w;
        }
        As[la_k + 0][la_m] = a.x;
        As[la_k + 1][la_m] = a.y;
        As[la_k + 2][la_m] = a.z;
        As[la_k + 3][la_m] = a.w;

        float4 w4 = *(const float4*)(W + (size_t)(k0 + lw_k) * N + bn + lw_n);
        *(float4*)&Ws[lw_k][lw_n] = w4;

        __syncthreads();
#pragma unroll
        for (int k = 0; k < 16; k++) {
            float4 av = *(const float4*)&As[k][ty * 4];
            float4 wv = *(const float4*)&Ws[k][tx * 4];
            float ar[4] = {av.x, av.y, av.z, av.w};
            float wr[4] = {wv.x, wv.y, wv.z, wv.w};
#pragma unroll
            for (int i = 0; i < 4; i++)
#pragma unroll
                for (int j = 0; j < 4; j++)
                    acc[i][j] = fmaf(ar[i], wr[j], acc[i][j]);
        }
        __syncthreads();
    }

#pragma unroll
    for (int i = 0; i < 4; i++) {
        const int m = bm + ty * 4 + i;
#pragma unroll
        for (int j = 0; j < 4; j++) {
            const int n = bn + tx * 4 + j;
            float v = acc[i][j] + bias[n];
            if (RESF) v += res[(size_t)m * N + n];
            if (RELUF) v = fmaxf(v, 0.f);
            C[(size_t)m * N + n] = v;
        }
    }
}

// ---------------- deformable sampling: one warp per (b, q, head) ----------------
__global__ void __launch_bounds__(256) sample_kernel(
    const float* __restrict__ value,   // [B*LQ, 8, 32]
    const float* __restrict__ offs,    // [B*LQ, 256]  (h, lvl, p, 2)
    const float* __restrict__ attnl,   // [B*LQ, 128]  (h, 16)
    const float* __restrict__ refp,    // [B*LQ, 4, 2]
    float* __restrict__ samp)          // [B*LQ, 256]  (h, 32)
{
    const int warp_id = (blockIdx.x * blockDim.x + threadIdx.x) >> 5;  // over M_ROWS*8
    const int lane = threadIdx.x & 31;
    const int h  = warp_id & 7;
    const int bq = warp_id >> 3;
    const int b  = bq / LQ;

    // softmax over 16 logits (lanes 0..15 hold one each)
    const float* al = attnl + ((size_t)bq * 8 + h) * 16;
    float logit = (lane < 16) ? al[lane] : -1e30f;
    float mx = logit;
#pragma unroll
    for (int o = 16; o; o >>= 1) mx = fmaxf(mx, __shfl_xor_sync(0xffffffffu, mx, o));
    float e = (lane < 16) ? __expf(logit - mx) : 0.f;
    float se = e;
#pragma unroll
    for (int o = 16; o; o >>= 1) se += __shfl_xor_sync(0xffffffffu, se, o);
    const float inv_se = 1.f / se;

    const float* op = offs + (size_t)bq * 256 + h * 32;
    const float* rp = refp + (size_t)bq * 8;
    const float* vbase = value + (size_t)b * LQ * 256 + h * 32 + lane;

    float acc = 0.f;
#pragma unroll
    for (int lvl = 0; lvl < 4; lvl++) {
        const int Hh = c_H[lvl], Ww = c_W[lvl], st = c_ST[lvl];
        const float invW = 1.f / (float)Ww, invH = 1.f / (float)Hh;  // exact (pow2)
        const float rx = rp[lvl * 2 + 0];
        const float ry = rp[lvl * 2 + 1];
        const float* vb = vbase + (size_t)st * 256;
#pragma unroll
        for (int p = 0; p < 4; p++) {
            const float ox = op[lvl * 8 + p * 2 + 0];
            const float oy = op[lvl * 8 + p * 2 + 1];
            const float lx = rx + ox * invW;
            const float ly = ry + oy * invH;
            const float x = lx * (float)Ww - 0.5f;
            const float y = ly * (float)Hh - 0.5f;
            const float w = __shfl_sync(0xffffffffu, e, lvl * 4 + p) * inv_se;

            const float x0f = floorf(x), y0f = floorf(y);
            const int x0 = (int)x0f, y0 = (int)y0f;
            const float wx1 = x - x0f, wy1 = y - y0f;
            const float wx0 = 1.f - wx1, wy0 = 1.f - wy1;

            const bool xv0 = (x0 >= 0) && (x0 < Ww);
            const bool xv1 = (x0 + 1 >= 0) && (x0 + 1 < Ww);
            const bool yv0 = (y0 >= 0) && (y0 < Hh);
            const bool yv1 = (y0 + 1 >= 0) && (y0 + 1 < Hh);

            float v00 = 0.f, v10 = 0.f, v01 = 0.f, v11 = 0.f;
            if (yv0) {
                const size_t base = (size_t)(y0 * Ww) * 256;
                if (xv0) v00 = vb[base + (size_t)x0 * 256];
                if (xv1) v10 = vb[base + (size_t)(x0 + 1) * 256];
            }
            if (yv1) {
                const size_t base = (size_t)((y0 + 1) * Ww) * 256;
                if (xv0) v01 = vb[base + (size_t)x0 * 256];
                if (xv1) v11 = vb[base + (size_t)(x0 + 1) * 256];
            }
            acc += w * (wx0 * wy0 * v00 + wx1 * wy0 * v10 +
                        wx0 * wy1 * v01 + wx1 * wy1 * v11);
        }
    }
    samp[(size_t)bq * 256 + h * 32 + lane] = acc;
}

// ---------------- layernorm over 256 cols: one block per row ----------------
__global__ void __launch_bounds__(256) ln_kernel(
    const float* __restrict__ in, const float* __restrict__ g,
    const float* __restrict__ b, float* __restrict__ out)
{
    const int row = blockIdx.x, t = threadIdx.x;
    const float x = in[(size_t)row * 256 + t];

    __shared__ float red[8];
    __shared__ float s_mu, s_rstd;

    float v = x;
#pragma unroll
    for (int o = 16; o; o >>= 1) v += __shfl_xor_sync(0xffffffffu, v, o);
    if ((t & 31) == 0) red[t >> 5] = v;
    __syncthreads();
    if (t == 0) {
        float s = 0.f;
#pragma unroll
        for (int i = 0; i < 8; i++) s += red[i];
        s_mu = s * (1.f / 256.f);
    }
    __syncthreads();

    const float d = x - s_mu;
    v = d * d;
#pragma unroll
    for (int o = 16; o; o >>= 1) v += __shfl_xor_sync(0xffffffffu, v, o);
    if ((t & 31) == 0) red[t >> 5] = v;
    __syncthreads();
    if (t == 0) {
        float s = 0.f;
#pragma unroll
        for (int i = 0; i < 8; i++) s += red[i];
        s_rstd = rsqrtf(s * (1.f / 256.f) + 1e-5f);
    }
    __syncthreads();

    out[(size_t)row * 256 + t] = d * s_rstd * g[t] + b[t];
}

// ---------------- launch ----------------
extern "C" void kernel_launch(void* const* d_in, const int* in_sizes, int n_in,
                              void* d_out, int out_size)
{
    const float* src    = (const float*)d_in[0];
    const float* pos    = (const float*)d_in[1];
    const float* refp   = (const float*)d_in[2];
    const float* W_off  = (const float*)d_in[3];
    const float* b_off  = (const float*)d_in[4];
    const float* W_attn = (const float*)d_in[5];
    const float* b_attn = (const float*)d_in[6];
    const float* W_val  = (const float*)d_in[7];
    const float* b_val  = (const float*)d_in[8];
    const float* W_out  = (const float*)d_in[9];
    const float* b_out  = (const float*)d_in[10];
    const float* ln1_g  = (const float*)d_in[11];
    const float* ln1_b  = (const float*)d_in[12];
    const float* W1     = (const float*)d_in[13];
    const float* b1     = (const float*)d_in[14];
    const float* W2     = (const float*)d_in[15];
    const float* b2     = (const float*)d_in[16];
    const float* ln2_g  = (const float*)d_in[17];
    const float* ln2_b  = (const float*)d_in[18];
    float* out = (float*)d_out;

    float *p_value, *p_offs, *p_attn, *p_samp, *p_t1, *p_h, *p_ffn, *p_t2;
    cudaGetSymbolAddress((void**)&p_value, g_value);
    cudaGetSymbolAddress((void**)&p_offs,  g_offs);
    cudaGetSymbolAddress((void**)&p_attn,  g_attn);
    cudaGetSymbolAddress((void**)&p_samp,  g_samp);
    cudaGetSymbolAddress((void**)&p_t1,    g_t1);
    cudaGetSymbolAddress((void**)&p_h,     g_h);
    cudaGetSymbolAddress((void**)&p_ffn,   g_ffn);
    cudaGetSymbolAddress((void**)&p_t2,    g_t2);

    const int M = M_ROWS;
    const dim3 blk(256);
    const int gy = M / 64;  // 680

    // value = src @ W_val + b_val
    gemm_kernel<false,false,false><<<dim3(256/64, gy), blk>>>(
        src, nullptr, W_val, b_val, nullptr, p_value, M, 256, 256);
    // offs = (src+pos) @ W_off + b_off
    gemm_kernel<true,false,false><<<dim3(256/64, gy), blk>>>(
        src, pos, W_off, b_off, nullptr, p_offs, M, 256, 256);
    // attn logits = (src+pos) @ W_attn + b_attn
    gemm_kernel<true,false,false><<<dim3(128/64, gy), blk>>>(
        src, pos, W_attn, b_attn, nullptr, p_attn, M, 128, 256);
    // deformable sampling
    sample_kernel<<<M, blk>>>(p_value, p_offs, p_attn, refp, p_samp);
    // t1 = samp @ W_out + b_out + src
    gemm_kernel<false,true,false><<<dim3(256/64, gy), blk>>>(
        p_samp, nullptr, W_out, b_out, src, p_t1, M, 256, 256);
    // h = LN1(t1)
    ln_kernel<<<M, blk>>>(p_t1, ln1_g, ln1_b, p_h);
    // ffn = relu(h @ W1 + b1)
    gemm_kernel<false,false,true><<<dim3(1024/64, gy), blk>>>(
        p_h, nullptr, W1, b1, nullptr, p_ffn, M, 1024, 256);
    // t2 = ffn @ W2 + b2 + h
    gemm_kernel<false,true,false><<<dim3(256/64, gy), blk>>>(
        p_ffn, nullptr, W2, b2, p_h, p_t2, M, 256, 1024);
    // out = LN2(t2)
    ln_kernel<<<M, blk>>>(p_t2, ln2_g, ln2_b, out);
}

// round 3
// speedup vs baseline: 2.6793x; 2.6793x over previous
#include <cuda_runtime.h>
#include <math.h>
#include <stdint.h>

// ---------------- problem constants ----------------
#define D_MODEL 256
#define D_FFN   1024
#define LQ      21760
#define BATCH   2
#define M_ROWS  (BATCH * LQ)   // 43520

__device__ __constant__ int c_H[4]  = {128, 64, 32, 16};
__device__ __constant__ int c_W[4]  = {128, 64, 32, 16};
__device__ __constant__ int c_ST[4] = {0, 16384, 20480, 21504};

// ---------------- scratch ----------------
__device__ float g_src32[(size_t)M_ROWS * D_MODEL];
__device__ float g_qsum [(size_t)M_ROWS * D_MODEL];
__device__ float g_value[(size_t)M_ROWS * D_MODEL];
__device__ float g_offs [(size_t)M_ROWS * D_MODEL];
__device__ float g_attn [(size_t)M_ROWS * 128];
__device__ float g_samp [(size_t)M_ROWS * D_MODEL];
__device__ float g_t1   [(size_t)M_ROWS * D_MODEL];
__device__ float g_h    [(size_t)M_ROWS * D_MODEL];
__device__ float g_h32  [(size_t)M_ROWS * D_MODEL];
__device__ float g_ffn  [(size_t)M_ROWS * D_FFN];
__device__ float g_t2   [(size_t)M_ROWS * D_MODEL];
__device__ float g_WvalT [256 * 256];
__device__ float g_WoffT [256 * 256];
__device__ float g_WattnT[128 * 256];
__device__ float g_WoutT [256 * 256];
__device__ float g_W1T   [1024 * 256];
__device__ float g_W2T   [256 * 1024];

// ---------------- helpers ----------------
__device__ __forceinline__ uint32_t smem_u32(const void* p) {
    uint32_t a;
    asm("{ .reg .u64 t; cvta.to.shared.u64 t, %1; cvt.u32.u64 %0, t; }" : "=r"(a) : "l"(p));
    return a;
}
__device__ __forceinline__ float rna_tf32(float x) {
    uint32_t u;
    asm("cvt.rna.tf32.f32 %0, %1;" : "=r"(u) : "f"(x));
    return __uint_as_float(u);
}
__device__ __forceinline__ void cpasync16(uint32_t dst, const void* src) {
    asm volatile("cp.async.cg.shared.global [%0], [%1], 16;" :: "r"(dst), "l"(src));
}
__device__ __forceinline__ void ldsm_x4(uint32_t& r0, uint32_t& r1, uint32_t& r2, uint32_t& r3, uint32_t addr) {
    asm volatile("ldmatrix.sync.aligned.m8n8.x4.shared.b16 {%0,%1,%2,%3}, [%4];"
        : "=r"(r0), "=r"(r1), "=r"(r2), "=r"(r3) : "r"(addr));
}
__device__ __forceinline__ void mma_tf32(float* d, const uint32_t* a, const uint32_t* b) {
    asm volatile("mma.sync.aligned.m16n8k8.row.col.f32.tf32.tf32.f32 "
        "{%0,%1,%2,%3}, {%4,%5,%6,%7}, {%8,%9}, {%0,%1,%2,%3};"
        : "+f"(d[0]), "+f"(d[1]), "+f"(d[2]), "+f"(d[3])
        : "r"(a[0]), "r"(a[1]), "r"(a[2]), "r"(a[3]), "r"(b[0]), "r"(b[1]));
}

// ---------------- tensor-core tf32 GEMM via mma.sync ----------------
// C[M,N] = A[M,K] @ W[K,N] + bias (+res) (relu) (round)
// A: [M,K] row-major, tf32-rounded. WT: [N,K] row-major, tf32-rounded.
// CTA tile 128x128, BK=32, 8 warps (2m x 4n -> 64x32 warp tile), 2-stage cp.async.
// Stage layout: A rows 128 x 128B, B rows 128 x 128B; SW128 chunk swizzle.
template <bool RESF, bool RELUF, bool ROUNDF>
__global__ void __launch_bounds__(256) gemm_mma(
    const float* __restrict__ A, const float* __restrict__ WT,
    const float* __restrict__ bias, const float* __restrict__ res,
    float* __restrict__ C, int N, int K)
{
    extern __shared__ char dynsm[];
    const uint32_t smBase = smem_u32(dynsm);
    const uint32_t smA0 = smBase;               // stage stride 32KB
    const uint32_t smB0 = smBase + 16384;

    const int tid = threadIdx.x;
    const int lane = tid & 31;
    const int wid = tid >> 5;
    const int wm = wid & 1;          // 0..1
    const int wn = wid >> 1;         // 0..3
    const int bm = blockIdx.y * 128;
    const int bn = blockIdx.x * 128;

    // ---- gmem->smem loader mapping: 1024 16B-chunks per tile pair / 256 thr = 4 each
    // chunk id = tid + i*256 ; row = id>>3 (0..127), ck = id&7
    const float* aG[4]; const float* bG[4];
    uint32_t sOff[4];
#pragma unroll
    for (int i = 0; i < 4; i++) {
        const int id = tid + i * 256;
        const int row = id >> 3, ck = id & 7;
        aG[i] = A  + (size_t)(bm + row) * K + ck * 4;
        bG[i] = WT + (size_t)(bn + row) * K + ck * 4;
        sOff[i] = row * 128 + ((ck ^ (row & 7)) * 16);
    }

    // ---- ldmatrix address precompute (per-lane), stage-relative
    const int lt = lane >> 3;      // tile index 0..3
    const int lr = lane & 7;       // row within tile
    // A: tile t -> rows +(t&1)*8, chunk +(t>>1)
    const int aRow = wm * 64 + (lt & 1) * 8 + lr;        // + mt*16 later
    const int aCk0 = (lt >> 1);                          // + ks*2 later
    // B: tile t -> rows +(t>>1)*8, chunk +(t&1)
    const int bRow = wn * 32 + (lt >> 1) * 8 + lr;       // + np*16 later
    const int bCk0 = (lt & 1);

    float acc[4][4][4];
#pragma unroll
    for (int i = 0; i < 4; i++)
#pragma unroll
        for (int j = 0; j < 4; j++)
#pragma unroll
            for (int k = 0; k < 4; k++) acc[i][j][k] = 0.f;

    const int Cs = K >> 5;

    // prologue: stages 0 and 1
#pragma unroll
    for (int i = 0; i < 4; i++) {
        cpasync16(smA0 + sOff[i], aG[i]);
        cpasync16(smB0 + sOff[i], bG[i]);
    }
    asm volatile("cp.async.commit_group;" ::: "memory");
#pragma unroll
    for (int i = 0; i < 4; i++) {
        cpasync16(smA0 + 32768 + sOff[i], aG[i] + 32);
        cpasync16(smB0 + 32768 + sOff[i], bG[i] + 32);
    }
    asm volatile("cp.async.commit_group;" ::: "memory");

    for (int c = 0; c < Cs; ++c) {
        const int st = c & 1;
        const uint32_t sA = smA0 + st * 32768;
        const uint32_t sB = smB0 + st * 32768;
        if (c == Cs - 1) asm volatile("cp.async.wait_group 0;" ::: "memory");
        else             asm volatile("cp.async.wait_group 1;" ::: "memory");
        __syncthreads();

#pragma unroll
        for (int ks = 0; ks < 4; ks++) {
            uint32_t af[4][4];   // [mtile][reg]
            uint32_t bf[4][2];   // [ntile][reg]
#pragma unroll
            for (int mt = 0; mt < 4; mt++) {
                const int row = aRow + mt * 16;
                const int ck = aCk0 + ks * 2;
                ldsm_x4(af[mt][0], af[mt][1], af[mt][2], af[mt][3],
                        sA + row * 128 + ((ck ^ (row & 7)) * 16));
            }
#pragma unroll
            for (int np = 0; np < 2; np++) {
                const int row = bRow + np * 16;
                const int ck = bCk0 + ks * 2;
                uint32_t r0, r1, r2, r3;
                ldsm_x4(r0, r1, r2, r3,
                        sB + row * 128 + ((ck ^ (row & 7)) * 16));
                bf[np * 2 + 0][0] = r0; bf[np * 2 + 0][1] = r1;
                bf[np * 2 + 1][0] = r2; bf[np * 2 + 1][1] = r3;
            }
#pragma unroll
            for (int mt = 0; mt < 4; mt++)
#pragma unroll
                for (int nt = 0; nt < 4; nt++)
                    mma_tf32(acc[mt][nt], af[mt], bf[nt]);
        }
        __syncthreads();

        if (c + 2 < Cs) {
            const int k0 = (c + 2) << 5;
#pragma unroll
            for (int i = 0; i < 4; i++) {
                cpasync16(sA + sOff[i], aG[i] + k0);
                cpasync16(sB + sOff[i], bG[i] + k0);
            }
            asm volatile("cp.async.commit_group;" ::: "memory");
        }
    }

    // ---- epilogue: fragment -> gmem
    const int r0base = bm + wm * 64 + (lane >> 2);
    const int cbase  = bn + wn * 32 + (lane & 3) * 2;
#pragma unroll
    for (int mt = 0; mt < 4; mt++) {
#pragma unroll
        for (int nt = 0; nt < 4; nt++) {
            const int col = cbase + nt * 8;
            const float bx = bias[col], by = bias[col + 1];
#pragma unroll
            for (int half = 0; half < 2; half++) {
                const int row = r0base + mt * 16 + half * 8;
                float vx = acc[mt][nt][half * 2 + 0] + bx;
                float vy = acc[mt][nt][half * 2 + 1] + by;
                if (RESF) {
                    const float* rp = res + (size_t)row * N + col;
                    vx += rp[0]; vy += rp[1];
                }
                if (RELUF) { vx = fmaxf(vx, 0.f); vy = fmaxf(vy, 0.f); }
                if (ROUNDF) { vx = rna_tf32(vx); vy = rna_tf32(vy); }
                *(float2*)(C + (size_t)row * N + col) = make_float2(vx, vy);
            }
        }
    }
}

// ---------------- prep: rounded src, rounded (src+pos) ----------------
__global__ void __launch_bounds__(256) prep_kernel(
    const float* __restrict__ src, const float* __restrict__ pos,
    float* __restrict__ src32, float* __restrict__ qsum, int n4)
{
    int i = blockIdx.x * blockDim.x + threadIdx.x;
    if (i >= n4) return;
    float4 s = ((const float4*)src)[i];
    float4 p = ((const float4*)pos)[i];
    float4 a, q;
    a.x = rna_tf32(s.x); a.y = rna_tf32(s.y); a.z = rna_tf32(s.z); a.w = rna_tf32(s.w);
    q.x = rna_tf32(s.x + p.x); q.y = rna_tf32(s.y + p.y);
    q.z = rna_tf32(s.z + p.z); q.w = rna_tf32(s.w + p.w);
    ((float4*)src32)[i] = a;
    ((float4*)qsum)[i] = q;
}

// ---------------- weight transpose + tf32 rounding ----------------
__global__ void __launch_bounds__(256) transpose_rna(
    const float* __restrict__ W, float* __restrict__ WT, int K, int N)
{
    __shared__ float tile[32][33];
    const int k0 = blockIdx.y * 32, n0 = blockIdx.x * 32;
    const int tx = threadIdx.x & 31, ty = threadIdx.x >> 5;  // 32x8
#pragma unroll
    for (int r = 0; r < 4; r++)
        tile[ty + r * 8][tx] = W[(size_t)(k0 + ty + r * 8) * N + n0 + tx];
    __syncthreads();
#pragma unroll
    for (int r = 0; r < 4; r++)
        WT[(size_t)(n0 + ty + r * 8) * K + k0 + tx] = rna_tf32(tile[tx][ty + r * 8]);
}

// ---------------- deformable sampling: one warp per (b, q, head) ----------------
__global__ void __launch_bounds__(256) sample_kernel(
    const float* __restrict__ value, const float* __restrict__ offs,
    const float* __restrict__ attnl, const float* __restrict__ refp,
    float* __restrict__ samp)
{
    const int warp_id = (blockIdx.x * blockDim.x + threadIdx.x) >> 5;
    const int lane = threadIdx.x & 31;
    const int h  = warp_id & 7;
    const int bq = warp_id >> 3;
    const int b  = bq / LQ;

    const float* al = attnl + ((size_t)bq * 8 + h) * 16;
    float logit = (lane < 16) ? al[lane] : -1e30f;
    float mx = logit;
#pragma unroll
    for (int o = 16; o; o >>= 1) mx = fmaxf(mx, __shfl_xor_sync(0xffffffffu, mx, o));
    float e = (lane < 16) ? __expf(logit - mx) : 0.f;
    float se = e;
#pragma unroll
    for (int o = 16; o; o >>= 1) se += __shfl_xor_sync(0xffffffffu, se, o);
    const float inv_se = 1.f / se;

    const float* op = offs + (size_t)bq * 256 + h * 32;
    const float* rp = refp + (size_t)bq * 8;
    const float* vbase = value + (size_t)b * LQ * 256 + h * 32 + lane;

    float acc = 0.f;
#pragma unroll
    for (int lvl = 0; lvl < 4; lvl++) {
        const int Hh = c_H[lvl], Ww = c_W[lvl], st = c_ST[lvl];
        const float invW = 1.f / (float)Ww, invH = 1.f / (float)Hh;
        const float rx = rp[lvl * 2 + 0];
        const float ry = rp[lvl * 2 + 1];
        const float* vb = vbase + (size_t)st * 256;
#pragma unroll
        for (int p = 0; p < 4; p++) {
            const float ox = op[lvl * 8 + p * 2 + 0];
            const float oy = op[lvl * 8 + p * 2 + 1];
            const float x = (rx + ox * invW) * (float)Ww - 0.5f;
            const float y = (ry + oy * invH) * (float)Hh - 0.5f;
            const float w = __shfl_sync(0xffffffffu, e, lvl * 4 + p) * inv_se;

            const float x0f = floorf(x), y0f = floorf(y);
            const int x0 = (int)x0f, y0 = (int)y0f;
            const float wx1 = x - x0f, wy1 = y - y0f;
            const float wx0 = 1.f - wx1, wy0 = 1.f - wy1;

            const bool xv0 = (x0 >= 0) && (x0 < Ww);
            const bool xv1 = (x0 + 1 >= 0) && (x0 + 1 < Ww);
            const bool yv0 = (y0 >= 0) && (y0 < Hh);
            const bool yv1 = (y0 + 1 >= 0) && (y0 + 1 < Hh);

            float v00 = 0.f, v10 = 0.f, v01 = 0.f, v11 = 0.f;
            if (yv0) {
                const int base = (y0 * Ww) * 256;
                if (xv0) v00 = vb[base + x0 * 256];
                if (xv1) v10 = vb[base + (x0 + 1) * 256];
            }
            if (yv1) {
                const int base = ((y0 + 1) * Ww) * 256;
                if (xv0) v01 = vb[base + x0 * 256];
                if (xv1) v11 = vb[base + (x0 + 1) * 256];
            }
            acc += w * (wx0 * wy0 * v00 + wx1 * wy0 * v10 +
                        wx0 * wy1 * v01 + wx1 * wy1 * v11);
        }
    }
    samp[(size_t)bq * 256 + h * 32 + lane] = rna_tf32(acc);
}

// ---------------- layernorm over 256 cols ----------------
template <bool WR32>
__global__ void __launch_bounds__(256) ln_kernel(
    const float* __restrict__ in, const float* __restrict__ g,
    const float* __restrict__ b, float* __restrict__ out, float* __restrict__ out32)
{
    const int row = blockIdx.x, t = threadIdx.x;
    const float x = in[(size_t)row * 256 + t];

    __shared__ float red[8];
    __shared__ float s_mu, s_rstd;

    float v = x;
#pragma unroll
    for (int o = 16; o; o >>= 1) v += __shfl_xor_sync(0xffffffffu, v, o);
    if ((t & 31) == 0) red[t >> 5] = v;
    __syncthreads();
    if (t == 0) {
        float s = 0.f;
#pragma unroll
        for (int i = 0; i < 8; i++) s += red[i];
        s_mu = s * (1.f / 256.f);
    }
    __syncthreads();

    const float d = x - s_mu;
    v = d * d;
#pragma unroll
    for (int o = 16; o; o >>= 1) v += __shfl_xor_sync(0xffffffffu, v, o);
    if ((t & 31) == 0) red[t >> 5] = v;
    __syncthreads();
    if (t == 0) {
        float s = 0.f;
#pragma unroll
        for (int i = 0; i < 8; i++) s += red[i];
        s_rstd = rsqrtf(s * (1.f / 256.f) + 1e-5f);
    }
    __syncthreads();

    const float y = d * s_rstd * g[t] + b[t];
    out[(size_t)row * 256 + t] = y;
    if (WR32) out32[(size_t)row * 256 + t] = rna_tf32(y);
}

// ---------------- launch ----------------
extern "C" void kernel_launch(void* const* d_in, const int* in_sizes, int n_in,
                              void* d_out, int out_size)
{
    const float* src    = (const float*)d_in[0];
    const float* pos    = (const float*)d_in[1];
    const float* refp   = (const float*)d_in[2];
    const float* W_off  = (const float*)d_in[3];
    const float* b_off  = (const float*)d_in[4];
    const float* W_attn = (const float*)d_in[5];
    const float* b_attn = (const float*)d_in[6];
    const float* W_val  = (const float*)d_in[7];
    const float* b_val  = (const float*)d_in[8];
    const float* W_out  = (const float*)d_in[9];
    const float* b_out  = (const float*)d_in[10];
    const float* ln1_g  = (const float*)d_in[11];
    const float* ln1_b  = (const float*)d_in[12];
    const float* W1     = (const float*)d_in[13];
    const float* b1     = (const float*)d_in[14];
    const float* W2     = (const float*)d_in[15];
    const float* b2     = (const float*)d_in[16];
    const float* ln2_g  = (const float*)d_in[17];
    const float* ln2_b  = (const float*)d_in[18];
    float* out = (float*)d_out;

    float *p_src32, *p_qsum, *p_value, *p_offs, *p_attn, *p_samp, *p_t1, *p_h, *p_h32, *p_ffn, *p_t2;
    float *p_WvalT, *p_WoffT, *p_WattnT, *p_WoutT, *p_W1T, *p_W2T;
    cudaGetSymbolAddress((void**)&p_src32, g_src32);
    cudaGetSymbolAddress((void**)&p_qsum,  g_qsum);
    cudaGetSymbolAddress((void**)&p_value, g_value);
    cudaGetSymbolAddress((void**)&p_offs,  g_offs);
    cudaGetSymbolAddress((void**)&p_attn,  g_attn);
    cudaGetSymbolAddress((void**)&p_samp,  g_samp);
    cudaGetSymbolAddress((void**)&p_t1,    g_t1);
    cudaGetSymbolAddress((void**)&p_h,     g_h);
    cudaGetSymbolAddress((void**)&p_h32,   g_h32);
    cudaGetSymbolAddress((void**)&p_ffn,   g_ffn);
    cudaGetSymbolAddress((void**)&p_t2,    g_t2);
    cudaGetSymbolAddress((void**)&p_WvalT, g_WvalT);
    cudaGetSymbolAddress((void**)&p_WoffT, g_WoffT);
    cudaGetSymbolAddress((void**)&p_WattnT,g_WattnT);
    cudaGetSymbolAddress((void**)&p_WoutT, g_WoutT);
    cudaGetSymbolAddress((void**)&p_W1T,   g_W1T);
    cudaGetSymbolAddress((void**)&p_W2T,   g_W2T);

    const int SMEM_BYTES = 2 * 32768;  // 64 KB (2 stages x (16KB A + 16KB B))
    cudaFuncSetAttribute(gemm_mma<false, false, false>, cudaFuncAttributeMaxDynamicSharedMemorySize, SMEM_BYTES);
    cudaFuncSetAttribute(gemm_mma<true,  false, false>, cudaFuncAttributeMaxDynamicSharedMemorySize, SMEM_BYTES);
    cudaFuncSetAttribute(gemm_mma<false, true,  true >, cudaFuncAttributeMaxDynamicSharedMemorySize, SMEM_BYTES);

    const int M = M_ROWS;
    const int MT = M / 128;  // 340

    // prep
    {
        int n4 = M * D_MODEL / 4;
        prep_kernel<<<(n4 + 255) / 256, 256>>>(src, pos, p_src32, p_qsum, n4);
    }
    // weight transposes (rounded to tf32)
    transpose_rna<<<dim3(256 / 32, 256 / 32), 256>>>(W_val,  p_WvalT,  256, 256);
    transpose_rna<<<dim3(256 / 32, 256 / 32), 256>>>(W_off,  p_WoffT,  256, 256);
    transpose_rna<<<dim3(128 / 32, 256 / 32), 256>>>(W_attn, p_WattnT, 256, 128);
    transpose_rna<<<dim3(256 / 32, 256 / 32), 256>>>(W_out,  p_WoutT,  256, 256);
    transpose_rna<<<dim3(1024 / 32, 256 / 32), 256>>>(W1,    p_W1T,    256, 1024);
    transpose_rna<<<dim3(256 / 32, 1024 / 32), 256>>>(W2,    p_W2T,    1024, 256);

    // value = src @ W_val + b_val
    gemm_mma<false, false, false><<<dim3(2, MT), 256, SMEM_BYTES>>>(
        p_src32, p_WvalT, b_val, nullptr, p_value, 256, 256);
    // offs = (src+pos) @ W_off + b_off
    gemm_mma<false, false, false><<<dim3(2, MT), 256, SMEM_BYTES>>>(
        p_qsum, p_WoffT, b_off, nullptr, p_offs, 256, 256);
    // attn logits
    gemm_mma<false, false, false><<<dim3(1, MT), 256, SMEM_BYTES>>>(
        p_qsum, p_WattnT, b_attn, nullptr, p_attn, 128, 256);
    // sampling
    sample_kernel<<<M, 256>>>(p_value, p_offs, p_attn, refp, p_samp);
    // t1 = samp @ W_out + b_out + src
    gemm_mma<true, false, false><<<dim3(2, MT), 256, SMEM_BYTES>>>(
        p_samp, p_WoutT, b_out, src, p_t1, 256, 256);
    // h = LN1(t1) (+ rounded copy)
    ln_kernel<true><<<M, 256>>>(p_t1, ln1_g, ln1_b, p_h, p_h32);
    // ffn = round(relu(h @ W1 + b1))
    gemm_mma<false, true, true><<<dim3(8, MT), 256, SMEM_BYTES>>>(
        p_h32, p_W1T, b1, nullptr, p_ffn, 1024, 256);
    // t2 = ffn @ W2 + b2 + h
    gemm_mma<true, false, false><<<dim3(2, MT), 256, SMEM_BYTES>>>(
        p_ffn, p_W2T, b2, p_h, p_t2, 256, 1024);
    // out = LN2(t2)
    ln_kernel<false><<<M, 256>>>(p_t2, ln2_g, ln2_b, out, nullptr);
}